// round 2
// baseline (speedup 1.0000x reference)
#include <cuda_runtime.h>
#include <cstdint>

// ---------------- problem constants ----------------
#define NN   50000
#define NE   800000
#define NG   50
#define DIN  256
#define DMID 128
#define DOUT 256
#define DE   128
#define DP   64

#define E1CAP 450000
#define E2CAP 65536
#define E3CAP 4096

// ---------------- static device scratch ----------------
// zeroed-every-launch buffer (floats + ints aliased), laid out contiguously
#define OFF_AGGH   0u
#define OFF_AGGEA  6400000u
#define OFF_AGGH2  12800000u
#define OFF_AGGE1  19200000u
#define OFF_AGG3G  22400000u
#define OFF_AGGE2G 22412800u
#define OFF_S1F    22416000u
#define OFF_S2F    22466000u
#define OFF_INDEG  22516000u
#define OFF_CNT    22566000u
#define ZTOTAL     22566016u

__device__ __align__(16) float d_zbuf[ZTOTAL];

// persistent scratch (no zeroing needed; fully overwritten before read)
#define SOFF_H1   0u
#define SOFF_X1   6400000u
#define SOFF_H2   12800000u
#define SOFF_X2   19200000u
#define SOFF_H3   25600000u
#define SOFF_E1C  38400000u
#define SOFF_E2C  42594304u
#define SOFF_WF   42856448u
#define SOFF_CF   42872832u
#define SOFF_WF2  42872960u
#define SOFF_CFE  42881152u
#define STOTAL    42881280u

__device__ __align__(16) float d_sbuf[STOTAL];

#define IOFF_E1LIST 0u
#define IOFF_E2LIST 450000u
#define IOFF_SRCE2  515536u
#define IOFF_DSTE2  581072u
#define IOFF_SLOTE2 646608u
#define IOFF_E3LIST 1446608u
#define IOFF_SRCE3  1450704u
#define IOFF_DSTE3  1454800u
#define IOFF_E1SLOT 1458896u
#define IOFF_S1LIST 1462992u
#define IOFF_S2LIST 1512992u
#define IOFF_MAST   1562992u
#define ITOTAL      1563056u

__device__ __align__(16) int d_ibuf[ITOTAL];

// ---------------- helpers ----------------
__device__ __forceinline__ void redv4(float* p, float a, float b, float c, float d) {
    asm volatile("red.global.add.v4.f32 [%0], {%1,%2,%3,%4};"
                 :: "l"(p), "f"(a), "f"(b), "f"(c), "f"(d) : "memory");
}

__device__ __forceinline__ int warp_compact(bool pred, int* counter) {
    // returns output slot for this lane (valid only when pred), -1 otherwise
    unsigned m = __ballot_sync(0xffffffffu, pred);
    if (!m) return -1;
    int lane = threadIdx.x & 31;
    int leader = __ffs(m) - 1;
    int base = 0;
    if (lane == leader) base = atomicAdd(counter, __popc(m));
    base = __shfl_sync(0xffffffffu, base, leader);
    return pred ? base + __popc(m & ((1u << lane) - 1u)) : -1;
}

// ---------------- zero kernel ----------------
__global__ void zero_k() {
    float4* p = reinterpret_cast<float4*>(d_zbuf);
    int n4 = ZTOTAL / 4;
    for (int i = blockIdx.x * blockDim.x + threadIdx.x; i < n4; i += gridDim.x * blockDim.x)
        p[i] = make_float4(0.f, 0.f, 0.f, 0.f);
}

// ---------------- generic gathered/scattered tiled GEMM ----------------
// C[idxC?][N] (op)= act( A[idxA?][K] @ B[K][N] (+bias) (+C) )
// flags: bit0 = accumulate into C, bit1 = relu
__global__ __launch_bounds__(128) void gemm_k(
    const float* __restrict__ A, const int* __restrict__ idxA,
    const float* __restrict__ B, const float* __restrict__ bias,
    float* __restrict__ C, const int* __restrict__ idxC,
    int M, const int* __restrict__ Mptr, int Mcap, int K, int N, int flags)
{
    if (Mptr) { M = *Mptr; if (M > Mcap) M = Mcap; }
    const int BM = 64, BN = 64, BK = 16;
    __shared__ float As[BK][BM];
    __shared__ float Bs[BK][BN];
    const int tid = threadIdx.x;
    const int tx = tid & 7;    // 8 col-groups of 8
    const int ty = tid >> 3;   // 16 row-groups of 4
    const int mTiles = (M + BM - 1) / BM;
    const int nTiles = N / BN;
    const int tiles = mTiles * nTiles;

    for (int t = blockIdx.x; t < tiles; t += gridDim.x) {
        const int mt = t / nTiles, nt = t % nTiles;
        const int m0 = mt * BM, n0 = nt * BN;
        float acc[4][8];
        #pragma unroll
        for (int i = 0; i < 4; i++)
            #pragma unroll
            for (int j = 0; j < 8; j++) acc[i][j] = 0.f;

        for (int k0 = 0; k0 < K; k0 += BK) {
            #pragma unroll
            for (int l = 0; l < 2; l++) {
                int s = tid + l * 128;
                int row = s >> 2, q = s & 3;
                int m = m0 + row;
                float4 v = make_float4(0.f, 0.f, 0.f, 0.f);
                if (m < M) {
                    int r = idxA ? idxA[m] : m;
                    v = *reinterpret_cast<const float4*>(A + (size_t)r * K + k0 + q * 4);
                }
                As[q * 4 + 0][row] = v.x;
                As[q * 4 + 1][row] = v.y;
                As[q * 4 + 2][row] = v.z;
                As[q * 4 + 3][row] = v.w;
            }
            #pragma unroll
            for (int l = 0; l < 2; l++) {
                int s = tid + l * 128;
                int kk = s >> 4, nq = s & 15;
                float4 v = *reinterpret_cast<const float4*>(B + (size_t)(k0 + kk) * N + n0 + nq * 4);
                *reinterpret_cast<float4*>(&Bs[kk][nq * 4]) = v;
            }
            __syncthreads();
            #pragma unroll
            for (int k = 0; k < BK; k++) {
                float4 a4 = *reinterpret_cast<const float4*>(&As[k][ty * 4]);
                float4 b0 = *reinterpret_cast<const float4*>(&Bs[k][tx * 8]);
                float4 b1 = *reinterpret_cast<const float4*>(&Bs[k][tx * 8 + 4]);
                float av[4] = {a4.x, a4.y, a4.z, a4.w};
                float bv[8] = {b0.x, b0.y, b0.z, b0.w, b1.x, b1.y, b1.z, b1.w};
                #pragma unroll
                for (int i = 0; i < 4; i++)
                    #pragma unroll
                    for (int j = 0; j < 8; j++)
                        acc[i][j] = fmaf(av[i], bv[j], acc[i][j]);
            }
            __syncthreads();
        }
        #pragma unroll
        for (int i = 0; i < 4; i++) {
            int m = m0 + ty * 4 + i;
            if (m >= M) continue;
            int r = idxC ? idxC[m] : m;
            float* cp = C + (size_t)r * N + n0 + tx * 8;
            #pragma unroll
            for (int j = 0; j < 8; j++) {
                float v = acc[i][j];
                if (flags & 1) v += cp[j];
                if (bias) v += bias[n0 + tx * 8 + j];
                if (flags & 2) v = fmaxf(v, 0.f);
                cp[j] = v;
            }
        }
    }
}

// ---------------- weight fusion ----------------
__global__ void prep_weights(const float* __restrict__ wproj, const float* __restrict__ bproj,
                             const float* __restrict__ wme1, const float* __restrict__ wee1,
                             const float* __restrict__ be1) {
    float* Wf  = d_sbuf + SOFF_WF;
    float* cf  = d_sbuf + SOFF_CF;
    float* Wf2 = d_sbuf + SOFF_WF2;
    float* cfe = d_sbuf + SOFF_CFE;
    int i = blockIdx.x;   // 0..DE-1
    int j = threadIdx.x;  // 0..DMID-1
    float s = 0.f;
    for (int k = 0; k < DP; k++) s = fmaf(wproj[i * DP + k], wme1[k * DMID + j], s);
    Wf[i * DMID + j] = s;
    if (j < DP) {
        float s2 = 0.f;
        for (int k = 0; k < DP; k++) s2 = fmaf(wproj[i * DP + k], wee1[k * DP + j], s2);
        Wf2[i * DP + j] = s2;
    }
    if (i == 0) {
        float c = 0.f;
        for (int k = 0; k < DP; k++) c = fmaf(bproj[k], wme1[k * DMID + j], c);
        cf[j] = c;
        if (j < DP) {
            float c2 = 0.f;
            for (int k = 0; k < DP; k++) c2 = fmaf(bproj[k], wee1[k * DP + j], c2);
            cfe[j] = c2 + be1[j];
        }
    }
}

// ---------------- set construction ----------------
__global__ void find_masters(const int* __restrict__ batch) {
    int n = blockIdx.x * blockDim.x + threadIdx.x;
    if (n >= NN) return;
    int g = batch[n];
    if (n == 0 || batch[n - 1] != g) d_ibuf[IOFF_MAST + g] = n;
}

__global__ void mark_masters() {
    int g = threadIdx.x;
    if (g < NG) ((int*)(d_zbuf + OFF_S2F))[d_ibuf[IOFF_MAST + g]] = 1;
}

__global__ void pass_e3(const int* __restrict__ src, const int* __restrict__ dst,
                        const int* __restrict__ batch) {
    int* cnt = (int*)(d_zbuf + OFF_CNT);
    int* s2f = (int*)(d_zbuf + OFF_S2F);
    int base = blockIdx.x * blockDim.x + threadIdx.x;
    int stride = gridDim.x * blockDim.x;
    for (int e = base; ; e += stride) {
        bool pred = false;
        int dd = -1, ss = -1;
        if (e < NE) {
            dd = dst[e];
            if (d_ibuf[IOFF_MAST + batch[dd]] == dd) { pred = true; ss = src[e]; }
        }
        int j = warp_compact(pred, cnt + 2);
        if (pred && j < E3CAP) {
            d_ibuf[IOFF_E3LIST + j] = e;
            d_ibuf[IOFF_SRCE3 + j] = ss;
            d_ibuf[IOFF_DSTE3 + j] = dd;
            s2f[ss] = 1;
        }
        if (__all_sync(0xffffffffu, e >= NE)) break;
    }
}

__global__ void pass_e2(const int* __restrict__ src, const int* __restrict__ dst) {
    int* cnt = (int*)(d_zbuf + OFF_CNT);
    int* s2f = (int*)(d_zbuf + OFF_S2F);
    int* s1f = (int*)(d_zbuf + OFF_S1F);
    int base = blockIdx.x * blockDim.x + threadIdx.x;
    int stride = gridDim.x * blockDim.x;
    for (int e = base; ; e += stride) {
        bool pred = false;
        int dd = -1, ss = -1;
        if (e < NE) {
            dd = dst[e];
            if (s2f[dd]) { pred = true; ss = src[e]; }
        }
        int j = warp_compact(pred, cnt + 1);
        if (pred && j < E2CAP) {
            d_ibuf[IOFF_E2LIST + j] = e;
            d_ibuf[IOFF_SRCE2 + j] = ss;
            d_ibuf[IOFF_DSTE2 + j] = dd;
            d_ibuf[IOFF_SLOTE2 + e] = j;
            s1f[ss] = 1;
        }
        if (__all_sync(0xffffffffu, e >= NE)) break;
    }
}

__global__ void compact_nodes() {
    int* cnt = (int*)(d_zbuf + OFF_CNT);
    int* s2f = (int*)(d_zbuf + OFF_S2F);
    int* s1f = (int*)(d_zbuf + OFF_S1F);
    int base = blockIdx.x * blockDim.x + threadIdx.x;
    int stride = gridDim.x * blockDim.x;
    for (int n = base; ; n += stride) {
        bool in = n < NN;
        int s2 = in ? s2f[n] : 0;
        int s1 = (in ? s1f[n] : 0) | s2;
        if (in) s1f[n] = s1;
        int j2 = warp_compact(s2 != 0, cnt + 4);
        if (s2) d_ibuf[IOFF_S2LIST + j2] = n;
        int j1 = warp_compact(s1 != 0, cnt + 3);
        if (s1) d_ibuf[IOFF_S1LIST + j1] = n;
        if (__all_sync(0xffffffffu, n >= NN)) break;
    }
}

__global__ void pass_e1(const int* __restrict__ dst) {
    int* cnt = (int*)(d_zbuf + OFF_CNT);
    int* s1f = (int*)(d_zbuf + OFF_S1F);
    int base = blockIdx.x * blockDim.x + threadIdx.x;
    int stride = gridDim.x * blockDim.x;
    for (int e = base; ; e += stride) {
        bool pred = (e < NE) && s1f[dst[e]];
        int j = warp_compact(pred, cnt);
        if (pred && j < E1CAP) d_ibuf[IOFF_E1LIST + j] = e;
        if (__all_sync(0xffffffffu, e >= NE)) break;
    }
}

__global__ void build_e1slot() {
    int* cnt = (int*)(d_zbuf + OFF_CNT);
    int n = min(cnt[2], E3CAP);
    for (int i = blockIdx.x * blockDim.x + threadIdx.x; i < n; i += gridDim.x * blockDim.x)
        d_ibuf[IOFF_E1SLOT + i] = d_ibuf[IOFF_SLOTE2 + d_ibuf[IOFF_E3LIST + i]];
}

// ---------------- scatter phases ----------------
__global__ void scatter_l1(const int* __restrict__ src, const int* __restrict__ dst,
                           const float* __restrict__ eattr) {
    int* cnt = (int*)(d_zbuf + OFF_CNT);
    int nE1 = min(cnt[0], E1CAP);
    float* aggH  = d_zbuf + OFF_AGGH;
    float* aggEA = d_zbuf + OFF_AGGEA;
    int* indeg   = (int*)(d_zbuf + OFF_INDEG);
    const float* h1 = d_sbuf + SOFF_H1;
    int lane = threadIdx.x & 31;
    int w = (blockIdx.x * blockDim.x + threadIdx.x) >> 5;
    int W = (gridDim.x * blockDim.x) >> 5;
    for (int i = w; i < nE1; i += W) {
        int e = d_ibuf[IOFF_E1LIST + i];
        int s = src[e], d = dst[e];
        float4 hv = *reinterpret_cast<const float4*>(h1 + (size_t)s * DMID + lane * 4);
        redv4(aggH + (size_t)d * DMID + lane * 4, hv.x, hv.y, hv.z, hv.w);
        float4 ev = *reinterpret_cast<const float4*>(eattr + (size_t)e * DE + lane * 4);
        redv4(aggEA + (size_t)d * DE + lane * 4, ev.x, ev.y, ev.z, ev.w);
        if (lane == 0) atomicAdd(&indeg[d], 1);
    }
}

__global__ void scatter_l2() {
    int* cnt = (int*)(d_zbuf + OFF_CNT);
    int nE2 = min(cnt[1], E2CAP);
    float* aggH2 = d_zbuf + OFF_AGGH2;
    float* aggE1 = d_zbuf + OFF_AGGE1;
    const float* h2  = d_sbuf + SOFF_H2;
    const float* e1c = d_sbuf + SOFF_E1C;
    int lane = threadIdx.x & 31;
    int w = (blockIdx.x * blockDim.x + threadIdx.x) >> 5;
    int W = (gridDim.x * blockDim.x) >> 5;
    for (int i = w; i < nE2; i += W) {
        int s = d_ibuf[IOFF_SRCE2 + i], d = d_ibuf[IOFF_DSTE2 + i];
        float4 hv = *reinterpret_cast<const float4*>(h2 + (size_t)s * DMID + lane * 4);
        redv4(aggH2 + (size_t)d * DMID + lane * 4, hv.x, hv.y, hv.z, hv.w);
        if (lane < 16) {
            float4 ev = *reinterpret_cast<const float4*>(e1c + (size_t)i * DP + lane * 4);
            redv4(aggE1 + (size_t)d * DP + lane * 4, ev.x, ev.y, ev.z, ev.w);
        }
    }
}

__global__ void scatter_l3(const int* __restrict__ batch) {
    int* cnt = (int*)(d_zbuf + OFF_CNT);
    int nE3 = min(cnt[2], E3CAP);
    float* agg3g  = d_zbuf + OFF_AGG3G;
    float* agge2g = d_zbuf + OFF_AGGE2G;
    const float* h3  = d_sbuf + SOFF_H3;
    const float* e2c = d_sbuf + SOFF_E2C;
    int lane = threadIdx.x & 31;
    int w = (blockIdx.x * blockDim.x + threadIdx.x) >> 5;
    int W = (gridDim.x * blockDim.x) >> 5;
    for (int i = w; i < nE3; i += W) {
        int s = d_ibuf[IOFF_SRCE3 + i], d = d_ibuf[IOFF_DSTE3 + i];
        int g = batch[d];
        #pragma unroll
        for (int h = 0; h < 2; h++) {
            float4 v = *reinterpret_cast<const float4*>(h3 + (size_t)s * DOUT + h * 128 + lane * 4);
            redv4(agg3g + (size_t)g * DOUT + h * 128 + lane * 4, v.x, v.y, v.z, v.w);
        }
        if (lane < 16) {
            float4 u = *reinterpret_cast<const float4*>(e2c + (size_t)i * DP + lane * 4);
            redv4(agge2g + (size_t)g * DP + lane * 4, u.x, u.y, u.z, u.w);
        }
    }
}

// ---------------- finalize elementwise ----------------
__global__ void finalize_x1(const float* __restrict__ bs1) {
    int* cnt = (int*)(d_zbuf + OFF_CNT);
    float* x1 = d_sbuf + SOFF_X1;
    const float* aggH = d_zbuf + OFF_AGGH;
    const int* indeg = (int*)(d_zbuf + OFF_INDEG);
    const float* cf = d_sbuf + SOFF_CF;
    int total = cnt[3] * DMID;
    for (int t = blockIdx.x * blockDim.x + threadIdx.x; t < total; t += gridDim.x * blockDim.x) {
        int i = t >> 7, c = t & 127;
        int n = d_ibuf[IOFF_S1LIST + i];
        size_t o = (size_t)n * DMID + c;
        x1[o] = fmaxf(x1[o] + aggH[o] + (float)indeg[n] * cf[c] + bs1[c], 0.f);
    }
}

__global__ void finalize_x2(const float* __restrict__ bs2) {
    int* cnt = (int*)(d_zbuf + OFF_CNT);
    float* x2 = d_sbuf + SOFF_X2;
    const float* aggH2 = d_zbuf + OFF_AGGH2;
    int total = cnt[4] * DMID;
    for (int t = blockIdx.x * blockDim.x + threadIdx.x; t < total; t += gridDim.x * blockDim.x) {
        int i = t >> 7, c = t & 127;
        int n = d_ibuf[IOFF_S2LIST + i];
        size_t o = (size_t)n * DMID + c;
        x2[o] = fmaxf(x2[o] + aggH2[o] + bs2[c], 0.f);
    }
}

// ---------------- final output ----------------
__global__ void final_out(const float* __restrict__ ws3, const float* __restrict__ bs3,
                          const float* __restrict__ wme3, float* __restrict__ out) {
    int g = blockIdx.x, j = threadIdx.x;  // 50 x 256
    int m = d_ibuf[IOFF_MAST + g];
    const float* x2 = d_sbuf + SOFF_X2;
    const float* agg3g = d_zbuf + OFF_AGG3G;
    const float* agge2g = d_zbuf + OFF_AGGE2G;
    float s = bs3[j] + agg3g[g * DOUT + j];
    const float* xr = x2 + (size_t)m * DMID;
    #pragma unroll 4
    for (int k = 0; k < DMID; k++) s = fmaf(xr[k], ws3[k * DOUT + j], s);
    const float* er = agge2g + g * DP;
    #pragma unroll 4
    for (int k = 0; k < DP; k++) s = fmaf(er[k], wme3[k * DOUT + j], s);
    out[(size_t)g * DOUT + j] = s;
}

// ---------------- host orchestration ----------------
extern "C" void kernel_launch(void* const* d_in, const int* in_sizes, int n_in,
                              void* d_out, int out_size) {
    const float* x         = (const float*)d_in[0];
    const int*   eidx      = (const int*)d_in[1];
    const float* edge_attr = (const float*)d_in[2];
    const int*   batch     = (const int*)d_in[3];
    const float* wproj     = (const float*)d_in[4];
    const float* bproj     = (const float*)d_in[5];
    const float* ws1  = (const float*)d_in[6],  *bs1 = (const float*)d_in[7];
    const float* wmx1 = (const float*)d_in[8],  *wme1 = (const float*)d_in[9];
    const float* wes1 = (const float*)d_in[10], *wed1 = (const float*)d_in[11];
    const float* wee1 = (const float*)d_in[12], *be1 = (const float*)d_in[13];
    const float* ws2  = (const float*)d_in[14], *bs2 = (const float*)d_in[15];
    const float* wmx2 = (const float*)d_in[16], *wme2 = (const float*)d_in[17];
    const float* wes2 = (const float*)d_in[18], *wed2 = (const float*)d_in[19];
    const float* wee2 = (const float*)d_in[20], *be2 = (const float*)d_in[21];
    const float* ws3  = (const float*)d_in[22], *bs3 = (const float*)d_in[23];
    const float* wmx3 = (const float*)d_in[24], *wme3 = (const float*)d_in[25];
    const float* wee3 = (const float*)d_in[28];
    (void)wee3; (void)n_in; (void)in_sizes; (void)d_in;

    const int* src = eidx;
    const int* dst = eidx + NE;

    void* pz; cudaGetSymbolAddress(&pz, d_zbuf);
    void* ps; cudaGetSymbolAddress(&ps, d_sbuf);
    void* pi; cudaGetSymbolAddress(&pi, d_ibuf);
    float* zb = (float*)pz;
    float* sb = (float*)ps;
    int*   ib = (int*)pi;

    float* aggH  = zb + OFF_AGGH;
    float* aggEA = zb + OFF_AGGEA;
    float* aggE1 = zb + OFF_AGGE1;
    int*   cnt   = (int*)(zb + OFF_CNT);
    float* h1  = sb + SOFF_H1;
    float* x1  = sb + SOFF_X1;
    float* h2  = sb + SOFF_H2;
    float* x2  = sb + SOFF_X2;
    float* h3  = sb + SOFF_H3;
    float* e1c = sb + SOFF_E1C;
    float* e2c = sb + SOFF_E2C;
    float* Wf  = sb + SOFF_WF;
    float* Wf2 = sb + SOFF_WF2;
    float* cfe = sb + SOFF_CFE;
    int* S1list = ib + IOFF_S1LIST;
    int* S2list = ib + IOFF_S2LIST;
    int* srcE2 = ib + IOFF_SRCE2;
    int* dstE2 = ib + IOFF_DSTE2;
    int* E2list = ib + IOFF_E2LIST;
    int* srcE3 = ib + IOFF_SRCE3;
    int* dstE3 = ib + IOFF_DSTE3;
    int* e1slot = ib + IOFF_E1SLOT;

    // --- phase 0: zero scratch, build sets, fuse weights ---
    zero_k<<<4096, 256>>>();
    find_masters<<<(NN + 255) / 256, 256>>>(batch);
    mark_masters<<<1, 64>>>();
    pass_e3<<<1024, 256>>>(src, dst, batch);
    pass_e2<<<1024, 256>>>(src, dst);
    compact_nodes<<<512, 256>>>();
    pass_e1<<<1024, 256>>>(dst);
    build_e1slot<<<16, 256>>>();
    prep_weights<<<DE, DMID>>>(wproj, bproj, wme1, wee1, be1);

    // --- layer 1 ---
    // h1 = x @ wmx1  (all nodes)
    gemm_k<<<1564, 128>>>(x, nullptr, wmx1, nullptr, h1, nullptr,
                          NN, nullptr, NN, DIN, DMID, 0);
    // x1[S1] = x[S1] @ ws1
    gemm_k<<<512, 128>>>(x, S1list, ws1, nullptr, x1, S1list,
                         0, cnt + 3, NN, DIN, DMID, 0);
    scatter_l1<<<2048, 256>>>(src, dst, edge_attr);
    // x1[S1] += aggEA[S1] @ Wf
    gemm_k<<<512, 128>>>(aggEA, S1list, Wf, nullptr, x1, S1list,
                         0, cnt + 3, NN, DE, DMID, 1);
    finalize_x1<<<1024, 256>>>(bs1);
    // e1c = relu(x[srcE2]@wes1 + x[dstE2]@wed1 + edge_attr[E2]@Wf2 + cfe)
    gemm_k<<<512, 128>>>(x, srcE2, wes1, nullptr, e1c, nullptr,
                         0, cnt + 1, E2CAP, DIN, DP, 0);
    gemm_k<<<512, 128>>>(x, dstE2, wed1, nullptr, e1c, nullptr,
                         0, cnt + 1, E2CAP, DIN, DP, 1);
    gemm_k<<<512, 128>>>(edge_attr, E2list, Wf2, cfe, e1c, nullptr,
                         0, cnt + 1, E2CAP, DE, DP, 3);

    // --- layer 2 ---
    gemm_k<<<512, 128>>>(x1, S1list, wmx2, nullptr, h2, S1list,
                         0, cnt + 3, NN, DMID, DMID, 0);
    scatter_l2<<<512, 256>>>();
    gemm_k<<<128, 128>>>(x1, S2list, ws2, nullptr, x2, S2list,
                         0, cnt + 4, NN, DMID, DMID, 0);
    gemm_k<<<128, 128>>>(aggE1, S2list, wme2, nullptr, x2, S2list,
                         0, cnt + 4, NN, DP, DMID, 1);
    finalize_x2<<<128, 256>>>(bs2);
    // e2c = relu(x1[srcE3]@wes2 + x1[dstE3]@wed2 + e1c[e1slot]@wee2 + be2)
    gemm_k<<<64, 128>>>(x1, srcE3, wes2, nullptr, e2c, nullptr,
                        0, cnt + 2, E3CAP, DMID, DP, 0);
    gemm_k<<<64, 128>>>(x1, dstE3, wed2, nullptr, e2c, nullptr,
                        0, cnt + 2, E3CAP, DMID, DP, 1);
    gemm_k<<<64, 128>>>(e1c, e1slot, wee2, be2, e2c, nullptr,
                        0, cnt + 2, E3CAP, DP, DP, 3);

    // --- layer 3 ---
    gemm_k<<<256, 128>>>(x2, S2list, wmx3, nullptr, h3, S2list,
                         0, cnt + 4, NN, DMID, DOUT, 0);
    scatter_l3<<<64, 256>>>(batch);
    final_out<<<NG, DOUT>>>(ws3, bs3, wme3, (float*)d_out);
    (void)out_size;
}

// round 3
// speedup vs baseline: 1.0690x; 1.0690x over previous
#include <cuda_runtime.h>
#include <cstdint>

#define NN   50000
#define NE   800000
#define NG   50
#define DIN  256
#define DMID 128
#define DOUT 256
#define DE   128
#define DP   64

#define E1CAP 450000
#define E2CAP 65536
#define E3CAP 4096

#define OFF_AGGX   0u
#define OFF_AGGEA  12800000u
#define OFF_AGGX1  19200000u
#define OFF_AGGE1  25600000u
#define OFF_AGG3G  28800000u
#define OFF_AGGE2G 28806400u
#define OFF_S1F    28809600u
#define OFF_S2F    28859600u
#define OFF_INDEG  28909600u
#define OFF_CNT    28959600u
#define ZTOTAL     28959616u

__device__ __align__(16) float d_zbuf[ZTOTAL];

#define SOFF_X1   0u
#define SOFF_X2   6400000u
#define SOFF_E1C  12800000u
#define SOFF_E2C  16994304u
#define SOFF_WF   17256448u
#define SOFF_CF   17272832u
#define SOFF_WF2  17272960u
#define SOFF_CFE  17281152u
#define STOTAL    17281216u

__device__ __align__(16) float d_sbuf[STOTAL];

#define IOFF_E1LIST 0u
#define IOFF_SRCE1  450000u
#define IOFF_DSTE1  900000u
#define IOFF_E2LIST 1350000u
#define IOFF_SRCE2  1415536u
#define IOFF_DSTE2  1481072u
#define IOFF_SLOTE2 1546608u
#define IOFF_E3LIST 2346608u
#define IOFF_SRCE3  2350704u
#define IOFF_DSTE3  2354800u
#define IOFF_GE3    2358896u
#define IOFF_E1SLOT 2362992u
#define IOFF_S1LIST 2367088u
#define IOFF_S2LIST 2417088u
#define IOFF_MAST   2467088u
#define ITOTAL      2467152u

__device__ __align__(16) int d_ibuf[ITOTAL];

__device__ __forceinline__ void redv4(float* p, float a, float b, float c, float d) {
    asm volatile("red.global.add.v4.f32 [%0], {%1,%2,%3,%4};"
                 :: "l"(p), "f"(a), "f"(b), "f"(c), "f"(d) : "memory");
}

__device__ __forceinline__ int warp_compact(bool pred, int* counter) {
    unsigned m = __ballot_sync(0xffffffffu, pred);
    if (!m) return -1;
    int lane = threadIdx.x & 31;
    int leader = __ffs(m) - 1;
    int base = 0;
    if (lane == leader) base = atomicAdd(counter, __popc(m));
    base = __shfl_sync(0xffffffffu, base, leader);
    return pred ? base + __popc(m & ((1u << lane) - 1u)) : -1;
}

__global__ void zero_small() {
    float4* p = reinterpret_cast<float4*>(d_zbuf + OFF_AGG3G);
    int n4 = (ZTOTAL - OFF_AGG3G) / 4;
    for (int i = blockIdx.x * blockDim.x + threadIdx.x; i < n4; i += gridDim.x * blockDim.x)
        p[i] = make_float4(0.f, 0.f, 0.f, 0.f);
}

__global__ void zero_rows() {
    int* cnt = (int*)(d_zbuf + OFF_CNT);
    int nS1 = cnt[3], nS2 = cnt[4];
    float4 z = make_float4(0.f, 0.f, 0.f, 0.f);
    int total1 = nS1 * 96;
    int total2 = nS2 * 48;
    int stride = gridDim.x * blockDim.x;
    for (int t = blockIdx.x * blockDim.x + threadIdx.x; t < total1; t += stride) {
        int i = t / 96, q = t - i * 96;
        int n = d_ibuf[IOFF_S1LIST + i];
        if (q < 64) reinterpret_cast<float4*>(d_zbuf + OFF_AGGX + (size_t)n * 256)[q] = z;
        else        reinterpret_cast<float4*>(d_zbuf + OFF_AGGEA + (size_t)n * 128)[q - 64] = z;
    }
    for (int t = blockIdx.x * blockDim.x + threadIdx.x; t < total2; t += stride) {
        int i = t / 48, q = t - i * 48;
        int n = d_ibuf[IOFF_S2LIST + i];
        if (q < 32) reinterpret_cast<float4*>(d_zbuf + OFF_AGGX1 + (size_t)n * 128)[q] = z;
        else        reinterpret_cast<float4*>(d_zbuf + OFF_AGGE1 + (size_t)n * 64)[q - 32] = z;
    }
}

// C[idxC?][N] (op)= act( A[idxA?][K] @ B[K][N] (+bias) (+C) ); flags bit0=acc, bit1=relu
__global__ __launch_bounds__(256) void gemm_k(
    const float* __restrict__ A, const int* __restrict__ idxA,
    const float* __restrict__ B, const float* __restrict__ bias,
    float* __restrict__ C, const int* __restrict__ idxC,
    int M, const int* __restrict__ Mptr, int Mcap, int K, int N, int flags)
{
    if (Mptr) { M = *Mptr; if (M > Mcap) M = Mcap; }
    const int BM = 128, BN = 64, BK = 16;
    __shared__ float As[BK][BM];
    __shared__ float Bs[BK][BN];
    const int tid = threadIdx.x;
    const int tx = tid & 7;
    const int ty = tid >> 3;
    const int mTiles = (M + BM - 1) / BM;
    const int nTiles = N / BN;
    const int tiles = mTiles * nTiles;

    for (int t = blockIdx.x; t < tiles; t += gridDim.x) {
        const int mt = t / nTiles, nt = t % nTiles;
        const int m0 = mt * BM, n0 = nt * BN;
        float acc[4][8];
        #pragma unroll
        for (int i = 0; i < 4; i++)
            #pragma unroll
            for (int j = 0; j < 8; j++) acc[i][j] = 0.f;

        for (int k0 = 0; k0 < K; k0 += BK) {
            #pragma unroll
            for (int l = 0; l < 2; l++) {
                int s = tid + l * 256;
                int row = s >> 2, q = s & 3;
                int m = m0 + row;
                float4 v = make_float4(0.f, 0.f, 0.f, 0.f);
                if (m < M) {
                    int r = idxA ? idxA[m] : m;
                    v = *reinterpret_cast<const float4*>(A + (size_t)r * K + k0 + q * 4);
                }
                As[q * 4 + 0][row] = v.x;
                As[q * 4 + 1][row] = v.y;
                As[q * 4 + 2][row] = v.z;
                As[q * 4 + 3][row] = v.w;
            }
            {
                int kk = tid >> 4, nq = tid & 15;
                float4 v = *reinterpret_cast<const float4*>(B + (size_t)(k0 + kk) * N + n0 + nq * 4);
                *reinterpret_cast<float4*>(&Bs[kk][nq * 4]) = v;
            }
            __syncthreads();
            #pragma unroll
            for (int k = 0; k < BK; k++) {
                float4 a4 = *reinterpret_cast<const float4*>(&As[k][ty * 4]);
                float4 b0 = *reinterpret_cast<const float4*>(&Bs[k][tx * 8]);
                float4 b1 = *reinterpret_cast<const float4*>(&Bs[k][tx * 8 + 4]);
                float av[4] = {a4.x, a4.y, a4.z, a4.w};
                float bv[8] = {b0.x, b0.y, b0.z, b0.w, b1.x, b1.y, b1.z, b1.w};
                #pragma unroll
                for (int i = 0; i < 4; i++)
                    #pragma unroll
                    for (int j = 0; j < 8; j++)
                        acc[i][j] = fmaf(av[i], bv[j], acc[i][j]);
            }
            __syncthreads();
        }
        #pragma unroll
        for (int i = 0; i < 4; i++) {
            int m = m0 + ty * 4 + i;
            if (m >= M) continue;
            int r = idxC ? idxC[m] : m;
            float* cp = C + (size_t)r * N + n0 + tx * 8;
            #pragma unroll
            for (int j = 0; j < 8; j++) {
                float v = acc[i][j];
                if (flags & 1) v += cp[j];
                if (bias) v += bias[n0 + tx * 8 + j];
                if (flags & 2) v = fmaxf(v, 0.f);
                cp[j] = v;
            }
        }
    }
}

__global__ void prep_weights(const float* __restrict__ wproj, const float* __restrict__ bproj,
                             const float* __restrict__ wme1, const float* __restrict__ wee1,
                             const float* __restrict__ be1) {
    float* Wf  = d_sbuf + SOFF_WF;
    float* cf  = d_sbuf + SOFF_CF;
    float* Wf2 = d_sbuf + SOFF_WF2;
    float* cfe = d_sbuf + SOFF_CFE;
    int i = blockIdx.x;
    int j = threadIdx.x;
    float s = 0.f;
    for (int k = 0; k < DP; k++) s = fmaf(wproj[i * DP + k], wme1[k * DMID + j], s);
    Wf[i * DMID + j] = s;
    if (j < DP) {
        float s2 = 0.f;
        for (int k = 0; k < DP; k++) s2 = fmaf(wproj[i * DP + k], wee1[k * DP + j], s2);
        Wf2[i * DP + j] = s2;
    }
    if (i == 0) {
        float c = 0.f;
        for (int k = 0; k < DP; k++) c = fmaf(bproj[k], wme1[k * DMID + j], c);
        cf[j] = c;
        if (j < DP) {
            float c2 = 0.f;
            for (int k = 0; k < DP; k++) c2 = fmaf(bproj[k], wee1[k * DP + j], c2);
            cfe[j] = c2 + be1[j];
        }
    }
}

__global__ void find_masters(const int* __restrict__ batch) {
    int n = blockIdx.x * blockDim.x + threadIdx.x;
    if (n >= NN) return;
    int g = batch[n];
    if (n == 0 || batch[n - 1] != g) {
        d_ibuf[IOFF_MAST + g] = n;
        ((int*)(d_zbuf + OFF_S2F))[n] = 1;
    }
}

__global__ void pass_e3(const int* __restrict__ src, const int* __restrict__ dst,
                        const int* __restrict__ batch) {
    int* cnt = (int*)(d_zbuf + OFF_CNT);
    int* s2f = (int*)(d_zbuf + OFF_S2F);
    int base = blockIdx.x * blockDim.x + threadIdx.x;
    int stride = gridDim.x * blockDim.x;
    for (int e = base; ; e += stride) {
        bool pred = false;
        int dd = -1, ss = -1, g = -1;
        if (e < NE) {
            dd = dst[e];
            g = batch[dd];
            if (d_ibuf[IOFF_MAST + g] == dd) { pred = true; ss = src[e]; }
        }
        int j = warp_compact(pred, cnt + 2);
        if (pred && j < E3CAP) {
            d_ibuf[IOFF_E3LIST + j] = e;
            d_ibuf[IOFF_SRCE3 + j] = ss;
            d_ibuf[IOFF_DSTE3 + j] = dd;
            d_ibuf[IOFF_GE3 + j] = g;
            s2f[ss] = 1;
        }
        if (__all_sync(0xffffffffu, e >= NE)) break;
    }
}

__global__ void pass_e2(const int* __restrict__ src, const int* __restrict__ dst) {
    int* cnt = (int*)(d_zbuf + OFF_CNT);
    int* s2f = (int*)(d_zbuf + OFF_S2F);
    int* s1f = (int*)(d_zbuf + OFF_S1F);
    int base = blockIdx.x * blockDim.x + threadIdx.x;
    int stride = gridDim.x * blockDim.x;
    for (int e = base; ; e += stride) {
        bool pred = false;
        int dd = -1, ss = -1;
        if (e < NE) {
            dd = dst[e];
            if (s2f[dd]) { pred = true; ss = src[e]; }
        }
        int j = warp_compact(pred, cnt + 1);
        if (pred && j < E2CAP) {
            d_ibuf[IOFF_E2LIST + j] = e;
            d_ibuf[IOFF_SRCE2 + j] = ss;
            d_ibuf[IOFF_DSTE2 + j] = dd;
            d_ibuf[IOFF_SLOTE2 + e] = j;
            s1f[ss] = 1;
        }
        if (__all_sync(0xffffffffu, e >= NE)) break;
    }
}

__global__ void compact_nodes() {
    int* cnt = (int*)(d_zbuf + OFF_CNT);
    int* s2f = (int*)(d_zbuf + OFF_S2F);
    int* s1f = (int*)(d_zbuf + OFF_S1F);
    int base = blockIdx.x * blockDim.x + threadIdx.x;
    int stride = gridDim.x * blockDim.x;
    for (int n = base; ; n += stride) {
        bool in = n < NN;
        int s2 = in ? s2f[n] : 0;
        int s1 = (in ? s1f[n] : 0) | s2;
        if (in) s1f[n] = s1;
        int j2 = warp_compact(s2 != 0, cnt + 4);
        if (s2) d_ibuf[IOFF_S2LIST + j2] = n;
        int j1 = warp_compact(s1 != 0, cnt + 3);
        if (s1) d_ibuf[IOFF_S1LIST + j1] = n;
        if (__all_sync(0xffffffffu, n >= NN)) break;
    }
}

__global__ void pass_e1(const int* __restrict__ src, const int* __restrict__ dst) {
    int* cnt = (int*)(d_zbuf + OFF_CNT);
    int* s1f = (int*)(d_zbuf + OFF_S1F);
    int base = blockIdx.x * blockDim.x + threadIdx.x;
    int stride = gridDim.x * blockDim.x;
    for (int e = base; ; e += stride) {
        bool pred = false;
        int dd = -1;
        if (e < NE) { dd = dst[e]; pred = s1f[dd] != 0; }
        int j = warp_compact(pred, cnt);
        if (pred && j < E1CAP) {
            d_ibuf[IOFF_E1LIST + j] = e;
            d_ibuf[IOFF_SRCE1 + j] = src[e];
            d_ibuf[IOFF_DSTE1 + j] = dd;
        }
        if (__all_sync(0xffffffffu, e >= NE)) break;
    }
}

__global__ void build_e1slot() {
    int* cnt = (int*)(d_zbuf + OFF_CNT);
    int n = min(cnt[2], E3CAP);
    for (int i = blockIdx.x * blockDim.x + threadIdx.x; i < n; i += gridDim.x * blockDim.x)
        d_ibuf[IOFF_E1SLOT + i] = d_ibuf[IOFF_SLOTE2 + d_ibuf[IOFF_E3LIST + i]];
}

__global__ void scatter_l1(const float* __restrict__ x, const float* __restrict__ eattr) {
    int* cnt = (int*)(d_zbuf + OFF_CNT);
    int nE1 = min(cnt[0], E1CAP);
    float* aggX  = d_zbuf + OFF_AGGX;
    float* aggEA = d_zbuf + OFF_AGGEA;
    int* indeg   = (int*)(d_zbuf + OFF_INDEG);
    int lane = threadIdx.x & 31;
    int w = (blockIdx.x * blockDim.x + threadIdx.x) >> 5;
    int W = (gridDim.x * blockDim.x) >> 5;
    for (int i = w; i < nE1; i += W) {
        int e = d_ibuf[IOFF_E1LIST + i];
        int s = d_ibuf[IOFF_SRCE1 + i];
        int d = d_ibuf[IOFF_DSTE1 + i];
        #pragma unroll
        for (int h = 0; h < 2; h++) {
            float4 v = *reinterpret_cast<const float4*>(x + (size_t)s * DIN + h * 128 + lane * 4);
            redv4(aggX + (size_t)d * DIN + h * 128 + lane * 4, v.x, v.y, v.z, v.w);
        }
        float4 ev = *reinterpret_cast<const float4*>(eattr + (size_t)e * DE + lane * 4);
        redv4(aggEA + (size_t)d * DE + lane * 4, ev.x, ev.y, ev.z, ev.w);
        if (lane == 0) atomicAdd(&indeg[d], 1);
    }
}

__global__ void scatter_l2() {
    int* cnt = (int*)(d_zbuf + OFF_CNT);
    int nE2 = min(cnt[1], E2CAP);
    float* aggX1 = d_zbuf + OFF_AGGX1;
    float* aggE1 = d_zbuf + OFF_AGGE1;
    const float* x1  = d_sbuf + SOFF_X1;
    const float* e1c = d_sbuf + SOFF_E1C;
    int lane = threadIdx.x & 31;
    int w = (blockIdx.x * blockDim.x + threadIdx.x) >> 5;
    int W = (gridDim.x * blockDim.x) >> 5;
    for (int i = w; i < nE2; i += W) {
        int s = d_ibuf[IOFF_SRCE2 + i], d = d_ibuf[IOFF_DSTE2 + i];
        float4 hv = *reinterpret_cast<const float4*>(x1 + (size_t)s * DMID + lane * 4);
        redv4(aggX1 + (size_t)d * DMID + lane * 4, hv.x, hv.y, hv.z, hv.w);
        if (lane < 16) {
            float4 ev = *reinterpret_cast<const float4*>(e1c + (size_t)i * DP + lane * 4);
            redv4(aggE1 + (size_t)d * DP + lane * 4, ev.x, ev.y, ev.z, ev.w);
        }
    }
}

__global__ void scatter_l3() {
    int* cnt = (int*)(d_zbuf + OFF_CNT);
    int nE3 = min(cnt[2], E3CAP);
    float* agg3g  = d_zbuf + OFF_AGG3G;
    float* agge2g = d_zbuf + OFF_AGGE2G;
    const float* x2  = d_sbuf + SOFF_X2;
    const float* e2c = d_sbuf + SOFF_E2C;
    int lane = threadIdx.x & 31;
    int w = (blockIdx.x * blockDim.x + threadIdx.x) >> 5;
    int W = (gridDim.x * blockDim.x) >> 5;
    for (int i = w; i < nE3; i += W) {
        int s = d_ibuf[IOFF_SRCE3 + i];
        int g = d_ibuf[IOFF_GE3 + i];
        float4 v = *reinterpret_cast<const float4*>(x2 + (size_t)s * DMID + lane * 4);
        redv4(agg3g + (size_t)g * DMID + lane * 4, v.x, v.y, v.z, v.w);
        if (lane < 16) {
            float4 u = *reinterpret_cast<const float4*>(e2c + (size_t)i * DP + lane * 4);
            redv4(agge2g + (size_t)g * DP + lane * 4, u.x, u.y, u.z, u.w);
        }
    }
}

__global__ void finalize_x1(const float* __restrict__ bs1) {
    int* cnt = (int*)(d_zbuf + OFF_CNT);
    float* x1 = d_sbuf + SOFF_X1;
    const int* indeg = (int*)(d_zbuf + OFF_INDEG);
    const float* cf = d_sbuf + SOFF_CF;
    int total = cnt[3] * DMID;
    for (int t = blockIdx.x * blockDim.x + threadIdx.x; t < total; t += gridDim.x * blockDim.x) {
        int i = t >> 7, c = t & 127;
        int n = d_ibuf[IOFF_S1LIST + i];
        size_t o = (size_t)n * DMID + c;
        x1[o] = fmaxf(x1[o] + (float)indeg[n] * cf[c] + bs1[c], 0.f);
    }
}

__global__ void finalize_x2(const float* __restrict__ bs2) {
    int* cnt = (int*)(d_zbuf + OFF_CNT);
    float* x2 = d_sbuf + SOFF_X2;
    int total = cnt[4] * DMID;
    for (int t = blockIdx.x * blockDim.x + threadIdx.x; t < total; t += gridDim.x * blockDim.x) {
        int i = t >> 7, c = t & 127;
        int n = d_ibuf[IOFF_S2LIST + i];
        size_t o = (size_t)n * DMID + c;
        x2[o] = fmaxf(x2[o] + bs2[c], 0.f);
    }
}

__global__ void final_out(const float* __restrict__ ws3, const float* __restrict__ bs3,
                          const float* __restrict__ wmx3, const float* __restrict__ wme3,
                          float* __restrict__ out) {
    int g = blockIdx.x, j = threadIdx.x;
    int m = d_ibuf[IOFF_MAST + g];
    const float* x2 = d_sbuf + SOFF_X2;
    const float* agg3g = d_zbuf + OFF_AGG3G;
    const float* agge2g = d_zbuf + OFF_AGGE2G;
    float s = bs3[j];
    const float* xr = x2 + (size_t)m * DMID;
    #pragma unroll 4
    for (int k = 0; k < DMID; k++) s = fmaf(xr[k], ws3[k * DOUT + j], s);
    const float* ar = agg3g + (size_t)g * DMID;
    #pragma unroll 4
    for (int k = 0; k < DMID; k++) s = fmaf(ar[k], wmx3[k * DOUT + j], s);
    const float* er = agge2g + (size_t)g * DP;
    #pragma unroll 4
    for (int k = 0; k < DP; k++) s = fmaf(er[k], wme3[k * DOUT + j], s);
    out[(size_t)g * DOUT + j] = s;
}

extern "C" void kernel_launch(void* const* d_in, const int* in_sizes, int n_in,
                              void* d_out, int out_size) {
    const float* x         = (const float*)d_in[0];
    const int*   eidx      = (const int*)d_in[1];
    const float* edge_attr = (const float*)d_in[2];
    const int*   batch     = (const int*)d_in[3];
    const float* wproj     = (const float*)d_in[4];
    const float* bproj     = (const float*)d_in[5];
    const float* ws1  = (const float*)d_in[6],  *bs1 = (const float*)d_in[7];
    const float* wmx1 = (const float*)d_in[8],  *wme1 = (const float*)d_in[9];
    const float* wes1 = (const float*)d_in[10], *wed1 = (const float*)d_in[11];
    const float* wee1 = (const float*)d_in[12], *be1 = (const float*)d_in[13];
    const float* ws2  = (const float*)d_in[14], *bs2 = (const float*)d_in[15];
    const float* wmx2 = (const float*)d_in[16], *wme2 = (const float*)d_in[17];
    const float* wes2 = (const float*)d_in[18], *wed2 = (const float*)d_in[19];
    const float* wee2 = (const float*)d_in[20], *be2 = (const float*)d_in[21];
    const float* ws3  = (const float*)d_in[22], *bs3 = (const float*)d_in[23];
    const float* wmx3 = (const float*)d_in[24], *wme3 = (const float*)d_in[25];
    (void)n_in; (void)in_sizes;

    const int* src = eidx;
    const int* dst = eidx + NE;

    void* pz; cudaGetSymbolAddress(&pz, d_zbuf);
    void* ps; cudaGetSymbolAddress(&ps, d_sbuf);
    void* pi; cudaGetSymbolAddress(&pi, d_ibuf);
    float* zb = (float*)pz;
    float* sb = (float*)ps;
    int*   ib = (int*)pi;

    float* aggX  = zb + OFF_AGGX;
    float* aggEA = zb + OFF_AGGEA;
    float* aggX1 = zb + OFF_AGGX1;
    float* aggE1 = zb + OFF_AGGE1;
    int*   cnt   = (int*)(zb + OFF_CNT);
    float* x1  = sb + SOFF_X1;
    float* x2  = sb + SOFF_X2;
    float* e1c = sb + SOFF_E1C;
    float* e2c = sb + SOFF_E2C;
    float* Wf  = sb + SOFF_WF;
    float* Wf2 = sb + SOFF_WF2;
    float* cfe = sb + SOFF_CFE;
    int* S1list = ib + IOFF_S1LIST;
    int* S2list = ib + IOFF_S2LIST;
    int* srcE2 = ib + IOFF_SRCE2;
    int* dstE2 = ib + IOFF_DSTE2;
    int* E2list = ib + IOFF_E2LIST;
    int* srcE3 = ib + IOFF_SRCE3;
    int* dstE3 = ib + IOFF_DSTE3;
    int* e1slot = ib + IOFF_E1SLOT;

    zero_small<<<160, 256>>>();
    find_masters<<<(NN + 255) / 256, 256>>>(batch);
    pass_e3<<<800, 256>>>(src, dst, batch);
    pass_e2<<<800, 256>>>(src, dst);
    compact_nodes<<<512, 256>>>();
    pass_e1<<<800, 256>>>(src, dst);
    build_e1slot<<<16, 256>>>();
    zero_rows<<<1024, 256>>>();
    prep_weights<<<DE, DMID>>>(wproj, bproj, wme1, wee1, be1);

    // --- layer 1 ---
    scatter_l1<<<2048, 256>>>(x, edge_attr);
    gemm_k<<<256, 256>>>(x, S1list, ws1, nullptr, x1, S1list,
                         0, cnt + 3, NN, DIN, DMID, 0);
    gemm_k<<<256, 256>>>(aggX, S1list, wmx1, nullptr, x1, S1list,
                         0, cnt + 3, NN, DIN, DMID, 1);
    gemm_k<<<256, 256>>>(aggEA, S1list, Wf, nullptr, x1, S1list,
                         0, cnt + 3, NN, DE, DMID, 1);
    finalize_x1<<<1024, 256>>>(bs1);
    gemm_k<<<160, 256>>>(x, srcE2, wes1, nullptr, e1c, nullptr,
                         0, cnt + 1, E2CAP, DIN, DP, 0);
    gemm_k<<<160, 256>>>(x, dstE2, wed1, nullptr, e1c, nullptr,
                         0, cnt + 1, E2CAP, DIN, DP, 1);
    gemm_k<<<160, 256>>>(edge_attr, E2list, Wf2, cfe, e1c, nullptr,
                         0, cnt + 1, E2CAP, DE, DP, 3);

    // --- layer 2 ---
    scatter_l2<<<512, 256>>>();
    gemm_k<<<32, 256>>>(x1, S2list, ws2, nullptr, x2, S2list,
                        0, cnt + 4, NN, DMID, DMID, 0);
    gemm_k<<<32, 256>>>(aggX1, S2list, wmx2, nullptr, x2, S2list,
                        0, cnt + 4, NN, DMID, DMID, 1);
    gemm_k<<<32, 256>>>(aggE1, S2list, wme2, nullptr, x2, S2list,
                        0, cnt + 4, NN, DP, DMID, 1);
    finalize_x2<<<128, 256>>>(bs2);
    gemm_k<<<16, 256>>>(x1, srcE3, wes2, nullptr, e2c, nullptr,
                        0, cnt + 2, E3CAP, DMID, DP, 0);
    gemm_k<<<16, 256>>>(x1, dstE3, wed2, nullptr, e2c, nullptr,
                        0, cnt + 2, E3CAP, DMID, DP, 1);
    gemm_k<<<16, 256>>>(e1c, e1slot, wee2, be2, e2c, nullptr,
                        0, cnt + 2, E3CAP, DP, DP, 3);

    // --- layer 3 ---
    scatter_l3<<<64, 256>>>();
    final_out<<<NG, DOUT>>>(ws3, bs3, wmx3, wme3, (float*)d_out);
    (void)out_size;
}

// round 4
// speedup vs baseline: 1.5978x; 1.4947x over previous
#include <cuda_runtime.h>
#include <cstdint>

#define NN   50000
#define NE   800000
#define NG   50
#define DIN  256
#define DMID 128
#define DOUT 256
#define DE   128
#define DP   64

#define E1CAP 450000
#define E2CAP 65536
#define E3CAP 4096

// ---------- zeroed-per-launch buffer ----------
#define OFF_AGGX   0u            // [NN][256] (written by gather, no zero needed)
#define OFF_AGGEA  12800000u     // [NN][128] (written by gather, no zero needed)
#define OFF_AGGX1  19200000u     // [NN][128] zeroed per-S2-row
#define OFF_AGGE1  25600000u     // [NN][64]  zeroed per-S2-row
#define OFF_AGG3G  28800000u     // from here on zeroed fully by zero_small
#define OFF_AGGE2G 28806400u
#define OFF_S1F    28809600u
#define OFF_S2F    28859600u
#define OFF_INDEG  28909600u
#define OFF_FILL   28959600u
#define OFF_CNT    29009600u     // 0:- 1:nE2 2:nE3 3:nS1 4:nS2 5:csr cursor
#define ZTOTAL     29009616u

__device__ __align__(16) float d_zbuf[ZTOTAL];

// ---------- persistent scratch ----------
#define SOFF_X1   0u
#define SOFF_X2   6400000u
#define SOFF_E1C  12800000u
#define SOFF_E2C  16994304u
#define SOFF_WF   17256448u
#define SOFF_CF   17272832u
#define SOFF_WF2  17272960u
#define SOFF_CFE  17281152u
#define STOTAL    17281216u

__device__ __align__(16) float d_sbuf[STOTAL];

#define IOFF_CSRSRC 0u
#define IOFF_CSREID 450000u
#define IOFF_START  900000u      // [NN]
#define IOFF_E2LIST 950000u
#define IOFF_SRCE2  1015536u
#define IOFF_DSTE2  1081072u
#define IOFF_SLOTE2 1146608u     // [NE]
#define IOFF_E3LIST 1946608u
#define IOFF_SRCE3  1950704u
#define IOFF_DSTE3  1954800u
#define IOFF_GE3    1958896u
#define IOFF_E1SLOT 1962992u
#define IOFF_S1LIST 1967088u
#define IOFF_S2LIST 2017088u
#define IOFF_MAST   2067088u
#define ITOTAL      2067152u

__device__ __align__(16) int d_ibuf[ITOTAL];

__device__ __forceinline__ void redv4(float* p, float a, float b, float c, float d) {
    asm volatile("red.global.add.v4.f32 [%0], {%1,%2,%3,%4};"
                 :: "l"(p), "f"(a), "f"(b), "f"(c), "f"(d) : "memory");
}

__device__ __forceinline__ unsigned f2tf32(float f) {
    unsigned u;
    asm("cvt.rna.tf32.f32 %0, %1;" : "=r"(u) : "f"(f));
    return u;
}

__device__ __forceinline__ int warp_compact(bool pred, int* counter) {
    unsigned m = __ballot_sync(0xffffffffu, pred);
    if (!m) return -1;
    int lane = threadIdx.x & 31;
    int leader = __ffs(m) - 1;
    int base = 0;
    if (lane == leader) base = atomicAdd(counter, __popc(m));
    base = __shfl_sync(0xffffffffu, base, leader);
    return pred ? base + __popc(m & ((1u << lane) - 1u)) : -1;
}

__global__ void zero_small() {
    float4* p = reinterpret_cast<float4*>(d_zbuf + OFF_AGG3G);
    int n4 = (ZTOTAL - OFF_AGG3G) / 4;
    for (int i = blockIdx.x * blockDim.x + threadIdx.x; i < n4; i += gridDim.x * blockDim.x)
        p[i] = make_float4(0.f, 0.f, 0.f, 0.f);
}

__global__ void zero_rows2() {
    int* cnt = (int*)(d_zbuf + OFF_CNT);
    int nS2 = cnt[4];
    float4 z = make_float4(0.f, 0.f, 0.f, 0.f);
    int total2 = nS2 * 48;
    int stride = gridDim.x * blockDim.x;
    for (int t = blockIdx.x * blockDim.x + threadIdx.x; t < total2; t += stride) {
        int i = t / 48, q = t - i * 48;
        int n = d_ibuf[IOFF_S2LIST + i];
        if (q < 32) reinterpret_cast<float4*>(d_zbuf + OFF_AGGX1 + (size_t)n * 128)[q] = z;
        else        reinterpret_cast<float4*>(d_zbuf + OFF_AGGE1 + (size_t)n * 64)[q - 32] = z;
    }
}

// ---------------- TF32 tensor-core GEMM ----------------
// C[idxC?][N] = act( A[idxA?][K] @ B[K][N] (+bias) (+C) ); flags bit0=acc, bit1=relu
__global__ __launch_bounds__(256) void gemm_k(
    const float* __restrict__ A, const int* __restrict__ idxA,
    const float* __restrict__ B, const float* __restrict__ bias,
    float* __restrict__ C, const int* __restrict__ idxC,
    int M, const int* __restrict__ Mptr, int Mcap, int K, int N, int flags)
{
    if (Mptr) { M = *Mptr; if (M > Mcap) M = Mcap; }
    const int BM = 128, BN = 64, BK = 16;
    __shared__ unsigned As[BK][BM + 4];   // stride 132: conflict-free frag loads
    __shared__ unsigned Bs[BK][BN + 4];   // stride 68
    const int tid = threadIdx.x;
    const int lane = tid & 31;
    const int warp = tid >> 5;            // 0..7
    const int wm = warp >> 1;             // 0..3
    const int wn = warp & 1;              // 0..1
    const int gid = lane >> 2;            // 0..7
    const int tg = lane & 3;              // 0..3
    const int mTiles = (M + BM - 1) / BM;
    const int nTiles = N / BN;
    const int tiles = mTiles * nTiles;

    for (int t = blockIdx.x; t < tiles; t += gridDim.x) {
        const int mt = t / nTiles, nt = t % nTiles;
        const int m0 = mt * BM, n0 = nt * BN;
        float c[2][4][4];
        #pragma unroll
        for (int mf = 0; mf < 2; mf++)
            #pragma unroll
            for (int nf = 0; nf < 4; nf++)
                #pragma unroll
                for (int q = 0; q < 4; q++) c[mf][nf][q] = 0.f;

        for (int k0 = 0; k0 < K; k0 += BK) {
            // A tile: 128 rows x 16 k, transposed store with tf32 convert
            #pragma unroll
            for (int l = 0; l < 2; l++) {
                int s = tid + l * 256;
                int row = s >> 2, q = s & 3;
                int m = m0 + row;
                float4 v = make_float4(0.f, 0.f, 0.f, 0.f);
                if (m < M) {
                    int r = idxA ? idxA[m] : m;
                    v = *reinterpret_cast<const float4*>(A + (size_t)r * K + k0 + q * 4);
                }
                As[q * 4 + 0][row] = f2tf32(v.x);
                As[q * 4 + 1][row] = f2tf32(v.y);
                As[q * 4 + 2][row] = f2tf32(v.z);
                As[q * 4 + 3][row] = f2tf32(v.w);
            }
            // B tile: 16 x 64
            {
                int kk = tid >> 4, nq = tid & 15;
                float4 v = *reinterpret_cast<const float4*>(B + (size_t)(k0 + kk) * N + n0 + nq * 4);
                Bs[kk][nq * 4 + 0] = f2tf32(v.x);
                Bs[kk][nq * 4 + 1] = f2tf32(v.y);
                Bs[kk][nq * 4 + 2] = f2tf32(v.z);
                Bs[kk][nq * 4 + 3] = f2tf32(v.w);
            }
            __syncthreads();
            #pragma unroll
            for (int kk = 0; kk < BK; kk += 8) {
                unsigned a[2][4], b[4][2];
                #pragma unroll
                for (int mf = 0; mf < 2; mf++) {
                    int am = wm * 32 + mf * 16;
                    a[mf][0] = As[kk + tg][am + gid];
                    a[mf][1] = As[kk + tg][am + gid + 8];
                    a[mf][2] = As[kk + tg + 4][am + gid];
                    a[mf][3] = As[kk + tg + 4][am + gid + 8];
                }
                #pragma unroll
                for (int nf = 0; nf < 4; nf++) {
                    int bn = wn * 32 + nf * 8;
                    b[nf][0] = Bs[kk + tg][bn + gid];
                    b[nf][1] = Bs[kk + tg + 4][bn + gid];
                }
                #pragma unroll
                for (int mf = 0; mf < 2; mf++)
                    #pragma unroll
                    for (int nf = 0; nf < 4; nf++)
                        asm volatile(
                            "mma.sync.aligned.m16n8k8.row.col.f32.tf32.tf32.f32 "
                            "{%0,%1,%2,%3},{%4,%5,%6,%7},{%8,%9},{%0,%1,%2,%3};"
                            : "+f"(c[mf][nf][0]), "+f"(c[mf][nf][1]),
                              "+f"(c[mf][nf][2]), "+f"(c[mf][nf][3])
                            : "r"(a[mf][0]), "r"(a[mf][1]), "r"(a[mf][2]), "r"(a[mf][3]),
                              "r"(b[nf][0]), "r"(b[nf][1]));
            }
            __syncthreads();
        }
        // epilogue
        #pragma unroll
        for (int mf = 0; mf < 2; mf++) {
            #pragma unroll
            for (int half = 0; half < 2; half++) {
                int mrow = m0 + wm * 32 + mf * 16 + gid + half * 8;
                if (mrow >= M) continue;
                int r = idxC ? idxC[mrow] : mrow;
                #pragma unroll
                for (int nf = 0; nf < 4; nf++) {
                    int col = n0 + wn * 32 + nf * 8 + tg * 2;
                    float* cp = C + (size_t)r * N + col;
                    float v0 = c[mf][nf][half * 2 + 0];
                    float v1 = c[mf][nf][half * 2 + 1];
                    if (flags & 1) {
                        float2 old = *reinterpret_cast<const float2*>(cp);
                        v0 += old.x; v1 += old.y;
                    }
                    if (bias) { v0 += bias[col]; v1 += bias[col + 1]; }
                    if (flags & 2) { v0 = fmaxf(v0, 0.f); v1 = fmaxf(v1, 0.f); }
                    *reinterpret_cast<float2*>(cp) = make_float2(v0, v1);
                }
            }
        }
    }
}

__global__ void prep_weights(const float* __restrict__ wproj, const float* __restrict__ bproj,
                             const float* __restrict__ wme1, const float* __restrict__ wee1,
                             const float* __restrict__ be1) {
    float* Wf  = d_sbuf + SOFF_WF;
    float* cf  = d_sbuf + SOFF_CF;
    float* Wf2 = d_sbuf + SOFF_WF2;
    float* cfe = d_sbuf + SOFF_CFE;
    int i = blockIdx.x;
    int j = threadIdx.x;
    float s = 0.f;
    for (int k = 0; k < DP; k++) s = fmaf(wproj[i * DP + k], wme1[k * DMID + j], s);
    Wf[i * DMID + j] = s;
    if (j < DP) {
        float s2 = 0.f;
        for (int k = 0; k < DP; k++) s2 = fmaf(wproj[i * DP + k], wee1[k * DP + j], s2);
        Wf2[i * DP + j] = s2;
    }
    if (i == 0) {
        float c = 0.f;
        for (int k = 0; k < DP; k++) c = fmaf(bproj[k], wme1[k * DMID + j], c);
        cf[j] = c;
        if (j < DP) {
            float c2 = 0.f;
            for (int k = 0; k < DP; k++) c2 = fmaf(bproj[k], wee1[k * DP + j], c2);
            cfe[j] = c2 + be1[j];
        }
    }
}

__global__ void find_masters(const int* __restrict__ batch) {
    int n = blockIdx.x * blockDim.x + threadIdx.x;
    if (n >= NN) return;
    int g = batch[n];
    if (n == 0 || batch[n - 1] != g) {
        d_ibuf[IOFF_MAST + g] = n;
        ((int*)(d_zbuf + OFF_S2F))[n] = 1;
    }
}

__global__ void pass_e3(const int* __restrict__ src, const int* __restrict__ dst,
                        const int* __restrict__ batch) {
    int* cnt = (int*)(d_zbuf + OFF_CNT);
    int* s2f = (int*)(d_zbuf + OFF_S2F);
    int base = blockIdx.x * blockDim.x + threadIdx.x;
    int stride = gridDim.x * blockDim.x;
    for (int e = base; ; e += stride) {
        bool pred = false;
        int dd = -1, ss = -1, g = -1;
        if (e < NE) {
            dd = dst[e];
            g = batch[dd];
            if (d_ibuf[IOFF_MAST + g] == dd) { pred = true; ss = src[e]; }
        }
        int j = warp_compact(pred, cnt + 2);
        if (pred && j < E3CAP) {
            d_ibuf[IOFF_E3LIST + j] = e;
            d_ibuf[IOFF_SRCE3 + j] = ss;
            d_ibuf[IOFF_DSTE3 + j] = dd;
            d_ibuf[IOFF_GE3 + j] = g;
            s2f[ss] = 1;
        }
        if (__all_sync(0xffffffffu, e >= NE)) break;
    }
}

__global__ void pass_e2(const int* __restrict__ src, const int* __restrict__ dst) {
    int* cnt = (int*)(d_zbuf + OFF_CNT);
    int* s2f = (int*)(d_zbuf + OFF_S2F);
    int* s1f = (int*)(d_zbuf + OFF_S1F);
    int base = blockIdx.x * blockDim.x + threadIdx.x;
    int stride = gridDim.x * blockDim.x;
    for (int e = base; ; e += stride) {
        bool pred = false;
        int dd = -1, ss = -1;
        if (e < NE) {
            dd = dst[e];
            if (s2f[dd]) { pred = true; ss = src[e]; }
        }
        int j = warp_compact(pred, cnt + 1);
        if (pred && j < E2CAP) {
            d_ibuf[IOFF_E2LIST + j] = e;
            d_ibuf[IOFF_SRCE2 + j] = ss;
            d_ibuf[IOFF_DSTE2 + j] = dd;
            d_ibuf[IOFF_SLOTE2 + e] = j;
            s1f[ss] = 1;
        }
        if (__all_sync(0xffffffffu, e >= NE)) break;
    }
}

__global__ void compact_nodes() {
    int* cnt = (int*)(d_zbuf + OFF_CNT);
    int* s2f = (int*)(d_zbuf + OFF_S2F);
    int* s1f = (int*)(d_zbuf + OFF_S1F);
    int base = blockIdx.x * blockDim.x + threadIdx.x;
    int stride = gridDim.x * blockDim.x;
    for (int n = base; ; n += stride) {
        bool in = n < NN;
        int s2 = in ? s2f[n] : 0;
        int s1 = (in ? s1f[n] : 0) | s2;
        if (in) s1f[n] = s1;
        int j2 = warp_compact(s2 != 0, cnt + 4);
        if (s2) d_ibuf[IOFF_S2LIST + j2] = n;
        int j1 = warp_compact(s1 != 0, cnt + 3);
        if (s1) d_ibuf[IOFF_S1LIST + j1] = n;
        if (__all_sync(0xffffffffu, n >= NN)) break;
    }
}

// count indegree over edges with dst in S1
__global__ void count_e1(const int* __restrict__ dst) {
    int* s1f = (int*)(d_zbuf + OFF_S1F);
    int* indeg = (int*)(d_zbuf + OFF_INDEG);
    int base = blockIdx.x * blockDim.x + threadIdx.x;
    int stride = gridDim.x * blockDim.x;
    for (int e = base; e < NE; e += stride) {
        int dd = dst[e];
        if (s1f[dd]) atomicAdd(&indeg[dd], 1);
    }
}

// assign contiguous CSR ranges per S1 node (order arbitrary)
__global__ void csr_assign() {
    int* cnt = (int*)(d_zbuf + OFF_CNT);
    int* indeg = (int*)(d_zbuf + OFF_INDEG);
    int nS1 = cnt[3];
    int base = blockIdx.x * blockDim.x + threadIdx.x;
    int stride = gridDim.x * blockDim.x;
    for (int i = base; i < nS1; i += stride) {
        int n = d_ibuf[IOFF_S1LIST + i];
        d_ibuf[IOFF_START + n] = atomicAdd(cnt + 5, indeg[n]);
    }
}

__global__ void fill_e1(const int* __restrict__ src, const int* __restrict__ dst) {
    int* s1f = (int*)(d_zbuf + OFF_S1F);
    int* fill = (int*)(d_zbuf + OFF_FILL);
    int base = blockIdx.x * blockDim.x + threadIdx.x;
    int stride = gridDim.x * blockDim.x;
    for (int e = base; e < NE; e += stride) {
        int dd = dst[e];
        if (s1f[dd]) {
            int pos = d_ibuf[IOFF_START + dd] + atomicAdd(&fill[dd], 1);
            if (pos < E1CAP) {
                d_ibuf[IOFF_CSRSRC + pos] = src[e];
                d_ibuf[IOFF_CSREID + pos] = e;
            }
        }
    }
}

__global__ void build_e1slot() {
    int* cnt = (int*)(d_zbuf + OFF_CNT);
    int n = min(cnt[2], E3CAP);
    for (int i = blockIdx.x * blockDim.x + threadIdx.x; i < n; i += gridDim.x * blockDim.x)
        d_ibuf[IOFF_E1SLOT + i] = d_ibuf[IOFF_SLOTE2 + d_ibuf[IOFF_E3LIST + i]];
}

// one warp per S1 node: register-accumulate x[src] (256) + edge_attr (128), write once
__global__ __launch_bounds__(256) void gather_l1(const float* __restrict__ x,
                                                 const float* __restrict__ eattr) {
    int* cnt = (int*)(d_zbuf + OFF_CNT);
    int nS1 = cnt[3];
    const int* indeg = (const int*)(d_zbuf + OFF_INDEG);
    float* aggX  = d_zbuf + OFF_AGGX;
    float* aggEA = d_zbuf + OFF_AGGEA;
    int lane = threadIdx.x & 31;
    int w = (blockIdx.x * blockDim.x + threadIdx.x) >> 5;
    int W = (gridDim.x * blockDim.x) >> 5;
    for (int i = w; i < nS1; i += W) {
        int n = d_ibuf[IOFF_S1LIST + i];
        int st = d_ibuf[IOFF_START + n];
        int end = st + indeg[n];
        if (end > E1CAP) end = E1CAP;
        float ax0 = 0.f, ax1 = 0.f, ax2 = 0.f, ax3 = 0.f;
        float ay0 = 0.f, ay1 = 0.f, ay2 = 0.f, ay3 = 0.f;
        float ae0 = 0.f, ae1 = 0.f, ae2 = 0.f, ae3 = 0.f;
        for (int base = st; base < end; base += 32) {
            int c = end - base; if (c > 32) c = 32;
            int msrc = 0, meid = 0;
            if (base + lane < end) {
                msrc = d_ibuf[IOFF_CSRSRC + base + lane];
                meid = d_ibuf[IOFF_CSREID + base + lane];
            }
            for (int j = 0; j < c; j++) {
                int s = __shfl_sync(0xffffffffu, msrc, j);
                int e = __shfl_sync(0xffffffffu, meid, j);
                float4 v0 = *reinterpret_cast<const float4*>(x + (size_t)s * DIN + lane * 4);
                float4 v1 = *reinterpret_cast<const float4*>(x + (size_t)s * DIN + 128 + lane * 4);
                float4 ev = *reinterpret_cast<const float4*>(eattr + (size_t)e * DE + lane * 4);
                ax0 += v0.x; ax1 += v0.y; ax2 += v0.z; ax3 += v0.w;
                ay0 += v1.x; ay1 += v1.y; ay2 += v1.z; ay3 += v1.w;
                ae0 += ev.x; ae1 += ev.y; ae2 += ev.z; ae3 += ev.w;
            }
        }
        *reinterpret_cast<float4*>(aggX + (size_t)n * DIN + lane * 4) =
            make_float4(ax0, ax1, ax2, ax3);
        *reinterpret_cast<float4*>(aggX + (size_t)n * DIN + 128 + lane * 4) =
            make_float4(ay0, ay1, ay2, ay3);
        *reinterpret_cast<float4*>(aggEA + (size_t)n * DE + lane * 4) =
            make_float4(ae0, ae1, ae2, ae3);
    }
}

__global__ void scatter_l2() {
    int* cnt = (int*)(d_zbuf + OFF_CNT);
    int nE2 = min(cnt[1], E2CAP);
    float* aggX1 = d_zbuf + OFF_AGGX1;
    float* aggE1 = d_zbuf + OFF_AGGE1;
    const float* x1  = d_sbuf + SOFF_X1;
    const float* e1c = d_sbuf + SOFF_E1C;
    int lane = threadIdx.x & 31;
    int w = (blockIdx.x * blockDim.x + threadIdx.x) >> 5;
    int W = (gridDim.x * blockDim.x) >> 5;
    for (int i = w; i < nE2; i += W) {
        int s = d_ibuf[IOFF_SRCE2 + i], d = d_ibuf[IOFF_DSTE2 + i];
        float4 hv = *reinterpret_cast<const float4*>(x1 + (size_t)s * DMID + lane * 4);
        redv4(aggX1 + (size_t)d * DMID + lane * 4, hv.x, hv.y, hv.z, hv.w);
        if (lane < 16) {
            float4 ev = *reinterpret_cast<const float4*>(e1c + (size_t)i * DP + lane * 4);
            redv4(aggE1 + (size_t)d * DP + lane * 4, ev.x, ev.y, ev.z, ev.w);
        }
    }
}

__global__ void scatter_l3() {
    int* cnt = (int*)(d_zbuf + OFF_CNT);
    int nE3 = min(cnt[2], E3CAP);
    float* agg3g  = d_zbuf + OFF_AGG3G;
    float* agge2g = d_zbuf + OFF_AGGE2G;
    const float* x2  = d_sbuf + SOFF_X2;
    const float* e2c = d_sbuf + SOFF_E2C;
    int lane = threadIdx.x & 31;
    int w = (blockIdx.x * blockDim.x + threadIdx.x) >> 5;
    int W = (gridDim.x * blockDim.x) >> 5;
    for (int i = w; i < nE3; i += W) {
        int s = d_ibuf[IOFF_SRCE3 + i];
        int g = d_ibuf[IOFF_GE3 + i];
        float4 v = *reinterpret_cast<const float4*>(x2 + (size_t)s * DMID + lane * 4);
        redv4(agg3g + (size_t)g * DMID + lane * 4, v.x, v.y, v.z, v.w);
        if (lane < 16) {
            float4 u = *reinterpret_cast<const float4*>(e2c + (size_t)i * DP + lane * 4);
            redv4(agge2g + (size_t)g * DP + lane * 4, u.x, u.y, u.z, u.w);
        }
    }
}

__global__ void finalize_x1(const float* __restrict__ bs1) {
    int* cnt = (int*)(d_zbuf + OFF_CNT);
    float* x1 = d_sbuf + SOFF_X1;
    const int* indeg = (int*)(d_zbuf + OFF_INDEG);
    const float* cf = d_sbuf + SOFF_CF;
    int total = cnt[3] * DMID;
    for (int t = blockIdx.x * blockDim.x + threadIdx.x; t < total; t += gridDim.x * blockDim.x) {
        int i = t >> 7, c = t & 127;
        int n = d_ibuf[IOFF_S1LIST + i];
        size_t o = (size_t)n * DMID + c;
        x1[o] = fmaxf(x1[o] + (float)indeg[n] * cf[c] + bs1[c], 0.f);
    }
}

__global__ void finalize_x2(const float* __restrict__ bs2) {
    int* cnt = (int*)(d_zbuf + OFF_CNT);
    float* x2 = d_sbuf + SOFF_X2;
    int total = cnt[4] * DMID;
    for (int t = blockIdx.x * blockDim.x + threadIdx.x; t < total; t += gridDim.x * blockDim.x) {
        int i = t >> 7, c = t & 127;
        int n = d_ibuf[IOFF_S2LIST + i];
        size_t o = (size_t)n * DMID + c;
        x2[o] = fmaxf(x2[o] + bs2[c], 0.f);
    }
}

__global__ void final_out(const float* __restrict__ ws3, const float* __restrict__ bs3,
                          const float* __restrict__ wmx3, const float* __restrict__ wme3,
                          float* __restrict__ out) {
    int g = blockIdx.x, j = threadIdx.x;
    int m = d_ibuf[IOFF_MAST + g];
    const float* x2 = d_sbuf + SOFF_X2;
    const float* agg3g = d_zbuf + OFF_AGG3G;
    const float* agge2g = d_zbuf + OFF_AGGE2G;
    float s = bs3[j];
    const float* xr = x2 + (size_t)m * DMID;
    #pragma unroll 4
    for (int k = 0; k < DMID; k++) s = fmaf(xr[k], ws3[k * DOUT + j], s);
    const float* ar = agg3g + (size_t)g * DMID;
    #pragma unroll 4
    for (int k = 0; k < DMID; k++) s = fmaf(ar[k], wmx3[k * DOUT + j], s);
    const float* er = agge2g + (size_t)g * DP;
    #pragma unroll 4
    for (int k = 0; k < DP; k++) s = fmaf(er[k], wme3[k * DOUT + j], s);
    out[(size_t)g * DOUT + j] = s;
}

extern "C" void kernel_launch(void* const* d_in, const int* in_sizes, int n_in,
                              void* d_out, int out_size) {
    const float* x         = (const float*)d_in[0];
    const int*   eidx      = (const int*)d_in[1];
    const float* edge_attr = (const float*)d_in[2];
    const int*   batch     = (const int*)d_in[3];
    const float* wproj     = (const float*)d_in[4];
    const float* bproj     = (const float*)d_in[5];
    const float* ws1  = (const float*)d_in[6],  *bs1 = (const float*)d_in[7];
    const float* wmx1 = (const float*)d_in[8],  *wme1 = (const float*)d_in[9];
    const float* wes1 = (const float*)d_in[10], *wed1 = (const float*)d_in[11];
    const float* wee1 = (const float*)d_in[12], *be1 = (const float*)d_in[13];
    const float* ws2  = (const float*)d_in[14], *bs2 = (const float*)d_in[15];
    const float* wmx2 = (const float*)d_in[16], *wme2 = (const float*)d_in[17];
    const float* wes2 = (const float*)d_in[18], *wed2 = (const float*)d_in[19];
    const float* wee2 = (const float*)d_in[20], *be2 = (const float*)d_in[21];
    const float* ws3  = (const float*)d_in[22], *bs3 = (const float*)d_in[23];
    const float* wmx3 = (const float*)d_in[24], *wme3 = (const float*)d_in[25];
    (void)n_in; (void)in_sizes;

    const int* src = eidx;
    const int* dst = eidx + NE;

    void* pz; cudaGetSymbolAddress(&pz, d_zbuf);
    void* ps; cudaGetSymbolAddress(&ps, d_sbuf);
    void* pi; cudaGetSymbolAddress(&pi, d_ibuf);
    float* zb = (float*)pz;
    float* sb = (float*)ps;
    int*   ib = (int*)pi;

    float* aggX  = zb + OFF_AGGX;
    float* aggEA = zb + OFF_AGGEA;
    float* aggX1 = zb + OFF_AGGX1;
    float* aggE1 = zb + OFF_AGGE1;
    int*   cnt   = (int*)(zb + OFF_CNT);
    float* x1  = sb + SOFF_X1;
    float* x2  = sb + SOFF_X2;
    float* e1c = sb + SOFF_E1C;
    float* e2c = sb + SOFF_E2C;
    float* Wf  = sb + SOFF_WF;
    float* Wf2 = sb + SOFF_WF2;
    float* cfe = sb + SOFF_CFE;
    int* S1list = ib + IOFF_S1LIST;
    int* S2list = ib + IOFF_S2LIST;
    int* srcE2 = ib + IOFF_SRCE2;
    int* dstE2 = ib + IOFF_DSTE2;
    int* E2list = ib + IOFF_E2LIST;
    int* srcE3 = ib + IOFF_SRCE3;
    int* dstE3 = ib + IOFF_DSTE3;
    int* e1slot = ib + IOFF_E1SLOT;

    zero_small<<<160, 256>>>();
    find_masters<<<(NN + 255) / 256, 256>>>(batch);
    pass_e3<<<800, 256>>>(src, dst, batch);
    pass_e2<<<800, 256>>>(src, dst);
    compact_nodes<<<512, 256>>>();
    count_e1<<<800, 256>>>(dst);
    csr_assign<<<64, 256>>>();
    fill_e1<<<800, 256>>>(src, dst);
    build_e1slot<<<16, 256>>>();
    zero_rows2<<<64, 256>>>();
    prep_weights<<<DE, DMID>>>(wproj, bproj, wme1, wee1, be1);

    // --- layer 1 ---
    gather_l1<<<1024, 256>>>(x, edge_attr);
    gemm_k<<<240, 256>>>(x, S1list, ws1, nullptr, x1, S1list,
                         0, cnt + 3, NN, DIN, DMID, 0);
    gemm_k<<<240, 256>>>(aggX, S1list, wmx1, nullptr, x1, S1list,
                         0, cnt + 3, NN, DIN, DMID, 1);
    gemm_k<<<240, 256>>>(aggEA, S1list, Wf, nullptr, x1, S1list,
                         0, cnt + 3, NN, DE, DMID, 1);
    finalize_x1<<<512, 256>>>(bs1);
    gemm_k<<<120, 256>>>(x, srcE2, wes1, nullptr, e1c, nullptr,
                         0, cnt + 1, E2CAP, DIN, DP, 0);
    gemm_k<<<120, 256>>>(x, dstE2, wed1, nullptr, e1c, nullptr,
                         0, cnt + 1, E2CAP, DIN, DP, 1);
    gemm_k<<<120, 256>>>(edge_attr, E2list, Wf2, cfe, e1c, nullptr,
                         0, cnt + 1, E2CAP, DE, DP, 3);

    // --- layer 2 ---
    scatter_l2<<<512, 256>>>();
    gemm_k<<<16, 256>>>(x1, S2list, ws2, nullptr, x2, S2list,
                        0, cnt + 4, NN, DMID, DMID, 0);
    gemm_k<<<16, 256>>>(aggX1, S2list, wmx2, nullptr, x2, S2list,
                        0, cnt + 4, NN, DMID, DMID, 1);
    gemm_k<<<16, 256>>>(aggE1, S2list, wme2, nullptr, x2, S2list,
                        0, cnt + 4, NN, DP, DMID, 1);
    finalize_x2<<<64, 256>>>(bs2);
    gemm_k<<<8, 256>>>(x1, srcE3, wes2, nullptr, e2c, nullptr,
                       0, cnt + 2, E3CAP, DMID, DP, 0);
    gemm_k<<<8, 256>>>(x1, dstE3, wed2, nullptr, e2c, nullptr,
                       0, cnt + 2, E3CAP, DMID, DP, 1);
    gemm_k<<<8, 256>>>(e1c, e1slot, wee2, be2, e2c, nullptr,
                       0, cnt + 2, E3CAP, DP, DP, 3);

    // --- layer 3 ---
    scatter_l3<<<64, 256>>>();
    final_out<<<NG, DOUT>>>(ws3, bs3, wmx3, wme3, (float*)d_out);
    (void)out_size;
}